// round 4
// baseline (speedup 1.0000x reference)
#include <cuda_runtime.h>
#include <cuda_bf16.h>
#include <stdint.h>

// ============================================================================
// Problem constants / layout
// ============================================================================
#define D 128
#define TILE_M 128

#define ROW_BF16   136            // padded bf16 row: 272 bytes (stride%128 = 16 -> ldmatrix conflict-free)
#define ROW_BYTES  272
#define STAGE_STRIDE 132          // fp32 stage row stride

// SMEM layout (bytes):
#define OFF_A_HI   0              // 128 x 136 bf16 = 34816
#define OFF_A_LO   34816
#define OFF_W_HI   69632
#define OFF_W_LO   104448
#define OFF_BIAS   139264         // 128 floats
#define SMEM_TOTAL 139776
// stage buffer (fp32 128 x 132 = 67584 B) reuses [0, 67584) after MMA.

// ============================================================================
// PTX helpers (base-ISA only: ldmatrix / mma.sync — compiles at plain sm_103)
// ============================================================================
__device__ __forceinline__ uint32_t smem_to_u32(const void* p) {
    uint32_t a;
    asm("{ .reg .u64 t; cvta.to.shared.u64 t, %1; cvt.u32.u64 %0, t; }" : "=r"(a) : "l"(p));
    return a;
}

#define LDSM4(r, addr) \
    asm volatile("ldmatrix.sync.aligned.m8n8.x4.shared.b16 {%0,%1,%2,%3}, [%4];" \
        : "=r"((r)[0]), "=r"((r)[1]), "=r"((r)[2]), "=r"((r)[3]) : "r"(addr))

#define MMA_BF16(c, a, b2) \
    asm volatile("mma.sync.aligned.m16n8k16.row.col.f32.bf16.bf16.f32 " \
        "{%0,%1,%2,%3},{%4,%5,%6,%7},{%8,%9},{%0,%1,%2,%3};" \
        : "+f"((c)[0]), "+f"((c)[1]), "+f"((c)[2]), "+f"((c)[3]) \
        : "r"((a)[0]), "r"((a)[1]), "r"((a)[2]), "r"((a)[3]), \
          "r"((b2)[0]), "r"((b2)[1]))

// ============================================================================
// Scratch: pre-split W (hi/lo bf16, unpadded [128][128], packed as uint32 pairs)
// ============================================================================
__device__ uint32_t g_W_hi[D * D / 2];  // 32 KB
__device__ uint32_t g_W_lo[D * D / 2];  // 32 KB

// fp32 -> (bf16 hi, bf16 lo) split, two values packed per uint32
__device__ __forceinline__ void split2(float x0, float x1, uint32_t& hi, uint32_t& lo) {
    __nv_bfloat16 h0 = __float2bfloat16_rn(x0);
    __nv_bfloat16 h1 = __float2bfloat16_rn(x1);
    __nv_bfloat16 l0 = __float2bfloat16_rn(x0 - __bfloat162float(h0));
    __nv_bfloat16 l1 = __float2bfloat16_rn(x1 - __bfloat162float(h1));
    hi = (uint32_t)__bfloat16_as_ushort(h0) | ((uint32_t)__bfloat16_as_ushort(h1) << 16);
    lo = (uint32_t)__bfloat16_as_ushort(l0) | ((uint32_t)__bfloat16_as_ushort(l1) << 16);
}

// ============================================================================
// Kernel 0 (merged prep): fill output with -inf AND split W into bf16 hi/lo.
// Merging keeps kernel_launch at 2 launches so ncu -s 5 -c 1 lands on fused.
// ============================================================================
__global__ void prep_kernel(int4* __restrict__ out, int n4, const float* __restrict__ W) {
    const int init_blocks = (n4 + 255) / 256;
    if ((int)blockIdx.x < init_blocks) {
        int i = blockIdx.x * 256 + threadIdx.x;
        if (i < n4) {
            const int m = 0xff800000;  // -inf
            out[i] = make_int4(m, m, m, m);
        }
    } else {
        int i = (blockIdx.x - init_blocks) * 256 + threadIdx.x;  // float4 index
        if (i < D * D / 4) {
            int row = i >> 5;
            int col = (i & 31) * 4;
            float4 x = reinterpret_cast<const float4*>(W)[i];
            uint32_t h01, l01, h23, l23;
            split2(x.x, x.y, h01, l01);
            split2(x.z, x.w, h23, l23);
            size_t boff = (size_t)row * 256 + (size_t)col * 2;
            *reinterpret_cast<uint2*>(reinterpret_cast<char*>(g_W_hi) + boff) = make_uint2(h01, h23);
            *reinterpret_cast<uint2*>(reinterpret_cast<char*>(g_W_lo) + boff) = make_uint2(l01, l23);
        }
    }
}

// ============================================================================
// Kernel 1: fused GEMM (mma.sync bf16 x3 split) + bias + relu + segment-max
// ============================================================================
__global__ __launch_bounds__(256, 1) void fused_kernel(
    const float* __restrict__ src,
    const float* __restrict__ b,
    const int* __restrict__ dst_idx,   // int32 (JAX x64-disabled downcasts int64)
    int* __restrict__ out,
    int E, int N)
{
    extern __shared__ __align__(16) char smem[];
    float* bias_s = reinterpret_cast<float*>(smem + OFF_BIAS);

    const int tid  = threadIdx.x;
    const int wid  = tid >> 5;
    const int lane = tid & 31;

    const int m_base = (wid & 3) * 32;   // warp M tile (rows)
    const int n_base = (wid >> 2) * 64;  // warp N tile (cols)

    const int tile_base = blockIdx.x * TILE_M;
    const int rem = min(TILE_M, E - tile_base);

    // ---- bias -> smem ----
    if (tid < D) bias_s[tid] = b[tid];

    // ---- copy pre-split W into padded SMEM rows ----
    {
        const uint4* gh = reinterpret_cast<const uint4*>(g_W_hi);
        const uint4* gl = reinterpret_cast<const uint4*>(g_W_lo);
        #pragma unroll
        for (int i = tid; i < 2048; i += 256) {  // 128 rows x 16 uint4
            int row = i >> 4, q = i & 15;
            size_t soff = (size_t)row * ROW_BYTES + (size_t)q * 16;
            *reinterpret_cast<uint4*>(smem + OFF_W_HI + soff) = gh[i];
            *reinterpret_cast<uint4*>(smem + OFF_W_LO + soff) = gl[i];
        }
    }

    // ---- convert src tile fp32 -> bf16 hi/lo into padded SMEM ----
    {
        const float4* srcT = reinterpret_cast<const float4*>(src + (size_t)tile_base * D);
        #pragma unroll
        for (int i = tid; i < TILE_M * D / 4; i += 256) {  // 4096 float4
            int row = i >> 5;
            int col = (i & 31) * 4;
            float4 x;
            if (row < rem) x = srcT[i];
            else x = make_float4(0.f, 0.f, 0.f, 0.f);
            uint32_t h01, l01, h23, l23;
            split2(x.x, x.y, h01, l01);
            split2(x.z, x.w, h23, l23);
            size_t soff = (size_t)row * ROW_BYTES + (size_t)col * 2;
            *reinterpret_cast<uint2*>(smem + OFF_A_HI + soff) = make_uint2(h01, h23);
            *reinterpret_cast<uint2*>(smem + OFF_A_LO + soff) = make_uint2(l01, l23);
        }
    }

    __syncthreads();

    // ---- ldmatrix base addresses ----
    const uint32_t sb = smem_to_u32(smem);
    // A (16x16 tiles): lane l -> row (l&15), k-half (l>>4)
    uint32_t aHi = sb + OFF_A_HI + (uint32_t)(m_base + (lane & 15)) * ROW_BYTES + (uint32_t)(lane >> 4) * 16;
    uint32_t aLo = aHi + (OFF_A_LO - OFF_A_HI);
    // B (n16 x k16 tiles, W rows are n-major/k-contiguous)
    const int bn = (lane & 7) | ((lane >> 4) << 3);
    uint32_t bHi = sb + OFF_W_HI + (uint32_t)(n_base + bn) * ROW_BYTES + (uint32_t)((lane >> 3) & 1) * 16;
    uint32_t bLo = bHi + (OFF_W_LO - OFF_W_HI);

    float acc[2][8][4];
    #pragma unroll
    for (int mt = 0; mt < 2; mt++)
        #pragma unroll
        for (int nt = 0; nt < 8; nt++)
            #pragma unroll
            for (int c = 0; c < 4; c++) acc[mt][nt][c] = 0.f;

    // ---- mainloop: K = 128 in 8 steps of k16; 3 mma passes: hh + lh + hl ----
    #pragma unroll
    for (int k = 0; k < 8; k++) {
        uint32_t ah[2][4], al[2][4], bh[4][4], bl[4][4];
        #pragma unroll
        for (int mt = 0; mt < 2; mt++) {
            LDSM4(ah[mt], aHi + (uint32_t)mt * 16 * ROW_BYTES + (uint32_t)k * 32);
            LDSM4(al[mt], aLo + (uint32_t)mt * 16 * ROW_BYTES + (uint32_t)k * 32);
        }
        #pragma unroll
        for (int np = 0; np < 4; np++) {
            LDSM4(bh[np], bHi + (uint32_t)np * 16 * ROW_BYTES + (uint32_t)k * 32);
            LDSM4(bl[np], bLo + (uint32_t)np * 16 * ROW_BYTES + (uint32_t)k * 32);
        }
        #pragma unroll
        for (int mt = 0; mt < 2; mt++) {
            #pragma unroll
            for (int nt = 0; nt < 8; nt++) {
                const uint32_t* Bh = &bh[nt >> 1][(nt & 1) * 2];
                const uint32_t* Bl = &bl[nt >> 1][(nt & 1) * 2];
                MMA_BF16(acc[mt][nt], ah[mt], Bh);
                MMA_BF16(acc[mt][nt], al[mt], Bh);
                MMA_BF16(acc[mt][nt], ah[mt], Bl);
            }
        }
    }

    __syncthreads();  // all warps done reading A smem -> safe to reuse as stage

    // ---- epilogue: bias + relu -> fp32 stage in SMEM ----
    {
        float* stage = reinterpret_cast<float*>(smem);
        const int r0 = m_base + (lane >> 2);
        const int cb = 2 * (lane & 3);
        #pragma unroll
        for (int mt = 0; mt < 2; mt++) {
            #pragma unroll
            for (int nt = 0; nt < 8; nt++) {
                int col = n_base + nt * 8 + cb;
                float bv0 = bias_s[col], bv1 = bias_s[col + 1];
                int rr = r0 + mt * 16;
                stage[rr * STAGE_STRIDE + col]           = fmaxf(acc[mt][nt][0] + bv0, 0.f);
                stage[rr * STAGE_STRIDE + col + 1]       = fmaxf(acc[mt][nt][1] + bv1, 0.f);
                stage[(rr + 8) * STAGE_STRIDE + col]     = fmaxf(acc[mt][nt][2] + bv0, 0.f);
                stage[(rr + 8) * STAGE_STRIDE + col + 1] = fmaxf(acc[mt][nt][3] + bv1, 0.f);
            }
        }
    }
    __syncthreads();

    // ---- scatter with monotonic read-filter ----
    // out values only increase (atomicMax). A pre-read that shows cur >= mine
    // proves the atomic would be a no-op -> skip. Stale reads are only ever
    // LOWER than truth -> never skip wrongly. Expected ~78% of atomics removed
    // (H(16)/16 winners per (node,col) under random arrival order).
    {
        const float* stage = reinterpret_cast<const float*>(smem);
        const int c0 = 4 * lane;  // lane owns cols [4*lane, 4*lane+4)
        for (int rr = wid; rr < rem; rr += 8) {
            int dst = dst_idx[tile_base + rr];
            if ((unsigned)dst >= (unsigned)N) continue;  // safety clamp
            const float4 mine = *reinterpret_cast<const float4*>(&stage[rr * STAGE_STRIDE + c0]);
            int* op = out + (size_t)dst * D + c0;
            const float4 cur = __ldcg(reinterpret_cast<const float4*>(op));
            // note: cur bits may be 0xFF800000 == -inf float; compare is correct
            if (mine.x > cur.x) atomicMax(op + 0, __float_as_int(mine.x));
            if (mine.y > cur.y) atomicMax(op + 1, __float_as_int(mine.y));
            if (mine.z > cur.z) atomicMax(op + 2, __float_as_int(mine.z));
            if (mine.w > cur.w) atomicMax(op + 3, __float_as_int(mine.w));
        }
    }
}

// ============================================================================
// Launch
// ============================================================================
extern "C" void kernel_launch(void* const* d_in, const int* in_sizes, int n_in,
                              void* d_out, int out_size) {
    const float* src     = (const float*)d_in[0];
    const float* W       = (const float*)d_in[1];
    const float* b       = (const float*)d_in[2];
    const int*   dst     = (const int*)d_in[3];   // int32 on device

    const int E = in_sizes[0] / D;
    const int N = out_size / D;
    const int tiles = (E + TILE_M - 1) / TILE_M;

    // 0: merged prep (init out to -inf + pre-split W)
    int n4 = out_size / 4;
    int init_blocks = (n4 + 255) / 256;
    int conv_blocks = (D * D / 4 + 255) / 256;
    prep_kernel<<<init_blocks + conv_blocks, 256>>>((int4*)d_out, n4, W);

    // 1: fused GEMM + filtered scatter-max
    cudaFuncSetAttribute(fused_kernel, cudaFuncAttributeMaxDynamicSharedMemorySize,
                         SMEM_TOTAL);
    fused_kernel<<<tiles, 256, SMEM_TOTAL>>>(src, b, dst, (int*)d_out, E, N);
}

// round 5
// speedup vs baseline: 1.9637x; 1.9637x over previous
#include <cuda_runtime.h>
#include <cuda_bf16.h>
#include <stdint.h>

// ============================================================================
// Problem constants / layout
// ============================================================================
#define D 128
#define TILE_M 128

#define ROW_BYTES  272            // padded bf16 row (136 bf16): stride%128=16 -> ldmatrix conflict-free
#define STAGE_STRIDE 132          // fp32 stage row stride

// SMEM layout (bytes): A tiles only; W comes from global fragment arrays.
#define OFF_A_HI   0              // 128 x 272B = 34816
#define OFF_A_LO   34816
#define OFF_BIAS   69632          // 128 floats
#define SMEM_TOTAL 70144
// stage buffer (fp32 128 x 132 = 67584 B) reuses [0, 67584) after MMA.

// ============================================================================
// PTX helpers (base-ISA only: ldmatrix / mma.sync — compiles at plain sm_103)
// ============================================================================
__device__ __forceinline__ uint32_t smem_to_u32(const void* p) {
    uint32_t a;
    asm("{ .reg .u64 t; cvta.to.shared.u64 t, %1; cvt.u32.u64 %0, t; }" : "=r"(a) : "l"(p));
    return a;
}

#define LDSM4(r, addr) \
    asm volatile("ldmatrix.sync.aligned.m8n8.x4.shared.b16 {%0,%1,%2,%3}, [%4];" \
        : "=r"((r)[0]), "=r"((r)[1]), "=r"((r)[2]), "=r"((r)[3]) : "r"(addr))

#define MMA_BF16(c, a, b0, b1) \
    asm volatile("mma.sync.aligned.m16n8k16.row.col.f32.bf16.bf16.f32 " \
        "{%0,%1,%2,%3},{%4,%5,%6,%7},{%8,%9},{%0,%1,%2,%3};" \
        : "+f"((c)[0]), "+f"((c)[1]), "+f"((c)[2]), "+f"((c)[3]) \
        : "r"((a)[0]), "r"((a)[1]), "r"((a)[2]), "r"((a)[3]), \
          "r"(b0), "r"(b1))

// ============================================================================
// W in B-fragment order: [kstep(8)][n8tile(16)][lane(32)] -> uint2 {b0, b1}
//   b0 = bf16x2( W[n][k0], W[n][k0+1] ),  b1 = same at k0+8
//   where n = n8t*8 + (lane>>2), k0 = kstep*16 + (lane&3)*2
// ============================================================================
__device__ uint2 g_Wf_hi[8 * 16 * 32];  // 32 KB
__device__ uint2 g_Wf_lo[8 * 16 * 32];  // 32 KB

// fp32 -> (bf16 hi, bf16 lo) split, two values packed per uint32
__device__ __forceinline__ void split2(float x0, float x1, uint32_t& hi, uint32_t& lo) {
    __nv_bfloat16 h0 = __float2bfloat16_rn(x0);
    __nv_bfloat16 h1 = __float2bfloat16_rn(x1);
    __nv_bfloat16 l0 = __float2bfloat16_rn(x0 - __bfloat162float(h0));
    __nv_bfloat16 l1 = __float2bfloat16_rn(x1 - __bfloat162float(h1));
    hi = (uint32_t)__bfloat16_as_ushort(h0) | ((uint32_t)__bfloat16_as_ushort(h1) << 16);
    lo = (uint32_t)__bfloat16_as_ushort(l0) | ((uint32_t)__bfloat16_as_ushort(l1) << 16);
}

// ============================================================================
// Kernel 0 (merged prep): init out to -inf AND pack W into fragment order.
// ============================================================================
__global__ void prep_kernel(int4* __restrict__ out, int n4, const float* __restrict__ W) {
    const int init_blocks = (n4 + 255) / 256;
    if ((int)blockIdx.x < init_blocks) {
        int i = blockIdx.x * 256 + threadIdx.x;
        if (i < n4) {
            const int m = 0xff800000;  // -inf
            out[i] = make_int4(m, m, m, m);
        }
    } else {
        int i = (blockIdx.x - init_blocks) * 256 + threadIdx.x;  // 0 .. 4095
        if (i < 8 * 16 * 32) {
            int lane = i & 31;
            int n8t  = (i >> 5) & 15;
            int kst  = i >> 9;
            int n  = n8t * 8 + (lane >> 2);
            int k0 = kst * 16 + (lane & 3) * 2;
            const float* Wr = W + (size_t)n * D;
            uint32_t h0, l0, h1, l1;
            split2(Wr[k0],     Wr[k0 + 1], h0, l0);
            split2(Wr[k0 + 8], Wr[k0 + 9], h1, l1);
            g_Wf_hi[i] = make_uint2(h0, h1);
            g_Wf_lo[i] = make_uint2(l0, l1);
        }
    }
}

// ============================================================================
// Kernel 1: fused GEMM (mma.sync bf16 x3 split) + bias + relu + segment-max
// ============================================================================
__global__ __launch_bounds__(256, 2) void fused_kernel(
    const float* __restrict__ src,
    const float* __restrict__ b,
    const int* __restrict__ dst_idx,   // int32 (JAX x64-disabled downcasts int64)
    int* __restrict__ out,
    int E, int N)
{
    extern __shared__ __align__(16) char smem[];
    float* bias_s = reinterpret_cast<float*>(smem + OFF_BIAS);

    const int tid  = threadIdx.x;
    const int wid  = tid >> 5;
    const int lane = tid & 31;

    const int m_base = (wid & 3) * 32;   // warp M tile (rows)
    const int n_base = (wid >> 2) * 64;  // warp N tile (cols)
    const int nb8    = n_base >> 3;      // first n8 tile index for this warp

    const int tile_base = blockIdx.x * TILE_M;
    const int rem = min(TILE_M, E - tile_base);

    // ---- bias -> smem ----
    if (tid < D) bias_s[tid] = b[tid];

    // ---- convert src tile fp32 -> bf16 hi/lo into padded SMEM ----
    {
        const float4* srcT = reinterpret_cast<const float4*>(src + (size_t)tile_base * D);
        #pragma unroll
        for (int i = tid; i < TILE_M * D / 4; i += 256) {  // 4096 float4
            int row = i >> 5;
            int col = (i & 31) * 4;
            float4 x;
            if (row < rem) x = srcT[i];
            else x = make_float4(0.f, 0.f, 0.f, 0.f);
            uint32_t h01, l01, h23, l23;
            split2(x.x, x.y, h01, l01);
            split2(x.z, x.w, h23, l23);
            size_t soff = (size_t)row * ROW_BYTES + (size_t)col * 2;
            *reinterpret_cast<uint2*>(smem + OFF_A_HI + soff) = make_uint2(h01, h23);
            *reinterpret_cast<uint2*>(smem + OFF_A_LO + soff) = make_uint2(l01, l23);
        }
    }

    __syncthreads();

    // ---- ldmatrix base addresses for A ----
    const uint32_t sb = smem_to_u32(smem);
    uint32_t aHi = sb + OFF_A_HI + (uint32_t)(m_base + (lane & 15)) * ROW_BYTES + (uint32_t)(lane >> 4) * 16;
    uint32_t aLo = aHi + (OFF_A_LO - OFF_A_HI);

    float acc[2][8][4];
    #pragma unroll
    for (int mt = 0; mt < 2; mt++)
        #pragma unroll
        for (int nt = 0; nt < 8; nt++)
            #pragma unroll
            for (int c = 0; c < 4; c++) acc[mt][nt][c] = 0.f;

    // ---- mainloop: K=128 in 8 k16 steps; B fragments streamed from global (L1-hot) ----
    #pragma unroll
    for (int k = 0; k < 8; k++) {
        uint32_t ah[2][4], al[2][4];
        #pragma unroll
        for (int mt = 0; mt < 2; mt++) {
            LDSM4(ah[mt], aHi + (uint32_t)mt * 16 * ROW_BYTES + (uint32_t)k * 32);
            LDSM4(al[mt], aLo + (uint32_t)mt * 16 * ROW_BYTES + (uint32_t)k * 32);
        }
        const int fbase = (k * 16 + nb8) * 32 + lane;
        #pragma unroll
        for (int nt = 0; nt < 8; nt++) {
            const uint2 Bh = g_Wf_hi[fbase + nt * 32];
            const uint2 Bl = g_Wf_lo[fbase + nt * 32];
            #pragma unroll
            for (int mt = 0; mt < 2; mt++) {
                MMA_BF16(acc[mt][nt], ah[mt], Bh.x, Bh.y);
                MMA_BF16(acc[mt][nt], al[mt], Bh.x, Bh.y);
                MMA_BF16(acc[mt][nt], ah[mt], Bl.x, Bl.y);
            }
        }
    }

    __syncthreads();  // all warps done reading A smem -> safe to reuse as stage

    // ---- epilogue: bias + relu -> fp32 stage in SMEM ----
    {
        float* stage = reinterpret_cast<float*>(smem);
        const int r0 = m_base + (lane >> 2);
        const int cb = 2 * (lane & 3);
        #pragma unroll
        for (int mt = 0; mt < 2; mt++) {
            #pragma unroll
            for (int nt = 0; nt < 8; nt++) {
                int col = n_base + nt * 8 + cb;
                float bv0 = bias_s[col], bv1 = bias_s[col + 1];
                int rr = r0 + mt * 16;
                stage[rr * STAGE_STRIDE + col]           = fmaxf(acc[mt][nt][0] + bv0, 0.f);
                stage[rr * STAGE_STRIDE + col + 1]       = fmaxf(acc[mt][nt][1] + bv1, 0.f);
                stage[(rr + 8) * STAGE_STRIDE + col]     = fmaxf(acc[mt][nt][2] + bv0, 0.f);
                stage[(rr + 8) * STAGE_STRIDE + col + 1] = fmaxf(acc[mt][nt][3] + bv1, 0.f);
            }
        }
    }
    __syncthreads();

    // ---- coalesced fire-and-forget atomicMax scatter (REDG: no return wait) ----
    {
        const float* stage = reinterpret_cast<const float*>(smem);
        for (int rr = wid; rr < rem; rr += 8) {
            int dst = dst_idx[tile_base + rr];
            if ((unsigned)dst >= (unsigned)N) continue;  // safety clamp
            int* op = out + (size_t)dst * D;
            #pragma unroll
            for (int kk = 0; kk < 4; kk++) {
                int col = lane + kk * 32;
                // relu => values >= 0; init 0xFF800000 => signed-int max == float max
                atomicMax(op + col, __float_as_int(stage[rr * STAGE_STRIDE + col]));
            }
        }
    }
}

// ============================================================================
// Launch
// ============================================================================
extern "C" void kernel_launch(void* const* d_in, const int* in_sizes, int n_in,
                              void* d_out, int out_size) {
    const float* src     = (const float*)d_in[0];
    const float* W       = (const float*)d_in[1];
    const float* b       = (const float*)d_in[2];
    const int*   dst     = (const int*)d_in[3];   // int32 on device

    const int E = in_sizes[0] / D;
    const int N = out_size / D;
    const int tiles = (E + TILE_M - 1) / TILE_M;

    // 0: merged prep (init out to -inf + pack W fragments)
    int n4 = out_size / 4;
    int init_blocks = (n4 + 255) / 256;
    int frag_blocks = (8 * 16 * 32 + 255) / 256;
    prep_kernel<<<init_blocks + frag_blocks, 256>>>((int4*)d_out, n4, W);

    // 1: fused GEMM + scatter-max
    cudaFuncSetAttribute(fused_kernel, cudaFuncAttributeMaxDynamicSharedMemorySize,
                         SMEM_TOTAL);
    fused_kernel<<<tiles, 256, SMEM_TOTAL>>>(src, b, dst, (int*)d_out, E, N);
}